// round 2
// baseline (speedup 1.0000x reference)
#include <cuda_runtime.h>
#include <cuda_bf16.h>
#include <cstdint>

// Problem constants
#define TT 1024
#define BB 128
#define HH 100
#define IN_ 100
#define GG 400   // 4*H

// ---------------- scratch (device globals: no allocs allowed) ----------------
__device__ float g_xT[(size_t)TT * BB * IN_];          // (T,B,IN)      52.4 MB
__device__ float g_gx[(size_t)2 * TT * BB * GG];       // (dir,T,B,4H) 419.4 MB
__device__ float g_mid[(size_t)TT * BB * 2 * HH];      // (T,B,2H)     104.9 MB

// ---------------- f32x2 helpers ----------------
__device__ __forceinline__ unsigned long long pk2(float a, float b) {
    unsigned long long r;
    asm("mov.b64 %0, {%1,%2};" : "=l"(r) : "f"(a), "f"(b));
    return r;
}
__device__ __forceinline__ unsigned long long fma2(unsigned long long a,
                                                   unsigned long long b,
                                                   unsigned long long c) {
    unsigned long long d;
    asm("fma.rn.f32x2 %0, %1, %2, %3;" : "=l"(d) : "l"(a), "l"(b), "l"(c));
    return d;
}
__device__ __forceinline__ float hsum2(unsigned long long a, unsigned long long b) {
    unsigned long long s;
    asm("add.rn.f32x2 %0, %1, %2;" : "=l"(s) : "l"(a), "l"(b));
    float lo, hi;
    asm("mov.b64 {%0,%1}, %2;" : "=f"(lo), "=f"(hi) : "l"(s));
    return lo + hi;
}

// ---------------- fast activations (MUFU-based, rel err ~1e-6) ----------------
__device__ __forceinline__ float fexp2(float x) {
    float r; asm("ex2.approx.f32 %0, %1;" : "=f"(r) : "f"(x)); return r;
}
__device__ __forceinline__ float frcpa(float x) {
    float r; asm("rcp.approx.f32 %0, %1;" : "=f"(r) : "f"(x)); return r;
}
__device__ __forceinline__ float fsig(float x) {
    return frcpa(1.0f + fexp2(-1.4426950408889634f * x));
}
__device__ __forceinline__ float ftanh(float x) {
    return fmaf(2.0f, frcpa(1.0f + fexp2(-2.8853900817779268f * x)), -1.0f);
}

// ---------------- kernel 1: transpose x (B,IN,T) -> xT (T,B,IN) ----------------
__global__ void transpose_x(const float* __restrict__ x, float* __restrict__ xT) {
    __shared__ float tile[32][33];
    int b  = blockIdx.z;
    int k0 = blockIdx.y * 32;
    int t0 = blockIdx.x * 32;
    int tx = threadIdx.x, ty = threadIdx.y;   // 32 x 8
    #pragma unroll
    for (int i = ty; i < 32; i += 8) {
        int k = k0 + i;
        tile[i][tx] = (k < IN_) ? x[((size_t)b * IN_ + k) * TT + (t0 + tx)] : 0.0f;
    }
    __syncthreads();
    #pragma unroll
    for (int i = ty; i < 32; i += 8) {
        int t = t0 + i, k = k0 + tx;
        if (k < IN_)
            xT[((size_t)t * BB + b) * IN_ + k] = tile[tx][i];
    }
}

// ---------------- kernel 2: gate GEMM, K-split register-stationary --------------
// 800 threads = 25 warps. Warp w: lanes 0-15 -> gates w*16+l (khalf 0),
// lanes 16-31 -> same gates (khalf 1). Each lane holds NBLK float4-blocks of
// W (<= 52 regs). Partial dots combined via shfl.bfly(16).
//   KF=100: blocks interleaved (2*i+kh), row padded to 104 floats (block 25 = 0)
//   KF=200: contiguous halves (kh*25+i), row = 200 floats
template<int KF>
__global__ __launch_bounds__(800, 1) void gate_gemm2(
    const float* __restrict__ src, int srcStride,
    const float* __restrict__ Wih, int wStride,
    const float* __restrict__ bias,
    float* __restrict__ out)
{
    constexpr int NBLK = (KF == 100) ? 13 : 25;
    constexpr int ROWF = (KF == 100) ? 104 : 200;
    constexpr int BPR  = ROWF / 4;       // float4 blocks per staged row
    constexpr int NLD  = 16 * BPR;       // staging loads per tile (<= 800)

    const int M   = TT * BB;             // 131072 rows per direction
    const int CPD = 74;
    const int RPC = 1776;                // rows per CTA, multiple of 16
    int dir   = blockIdx.x / CPD;
    int chunk = blockIdx.x % CPD;
    int row0  = chunk * RPC;
    int rowHi = min(row0 + RPC, M);

    int tid = threadIdx.x;
    int wp  = tid >> 5, ln = tid & 31;
    int j   = wp * 16 + (ln & 15);       // gate index 0..399
    int kh  = ln >> 4;                   // K-half

    __shared__ float stage[16][ROWF];

    // stationary weights
    unsigned long long w[2 * NBLK];
    {
        const float* wrow = Wih + (size_t)(dir * GG + j) * wStride;
        #pragma unroll
        for (int i = 0; i < NBLK; i++) {
            int col = (KF == 100) ? (8 * i + 4 * kh) : (kh * 100 + 4 * i);
            float4 t = make_float4(0.f, 0.f, 0.f, 0.f);
            if (col < KF) t = *(const float4*)(wrow + col);
            w[2 * i]     = pk2(t.x, t.y);
            w[2 * i + 1] = pk2(t.z, t.w);
        }
    }
    float bj = bias[dir * GG + j];

    // staging map + first prefetch
    int r_ld = tid / BPR;
    int c_ld = (tid % BPR) * 4;
    float4 v = make_float4(0.f, 0.f, 0.f, 0.f);
    if (tid < NLD && c_ld < KF) {
        int rr = min(row0 + r_ld, M - 1);
        v = *(const float4*)(src + (size_t)rr * srcStride + c_ld);
    }

    int ntiles = (rowHi - row0 + 15) / 16;
    for (int tI = 0; tI < ntiles; tI++) {
        __syncthreads();
        if (tid < NLD) *(float4*)&stage[r_ld][c_ld] = v;
        __syncthreads();
        if (tid < NLD && c_ld < KF && tI + 1 < ntiles) {
            int rr = min(row0 + (tI + 1) * 16 + r_ld, M - 1);
            v = *(const float4*)(src + (size_t)rr * srcStride + c_ld);
        }
        int rlim = min(16, rowHi - row0 - tI * 16);
        for (int r = 0; r < rlim; r++) {
            unsigned long long a0 = 0, a1 = 0;
            #pragma unroll
            for (int i = 0; i < NBLK; i++) {
                int off = (KF == 100) ? (8 * i + 4 * kh) : (kh * 100 + 4 * i);
                ulonglong2 hv = *(const ulonglong2*)&stage[r][off];
                a0 = fma2(w[2 * i],     hv.x, a0);
                a1 = fma2(w[2 * i + 1], hv.y, a1);
            }
            float g = hsum2(a0, a1);
            g += __shfl_xor_sync(0xffffffffu, g, 16);
            if ((ln & 16) == 0) {
                size_t orow = (size_t)(row0 + tI * 16 + r);
                out[((size_t)dir * M + orow) * GG + j] = g + bj;
            }
        }
    }
}

// ---------------- kernel 3: recurrence scan (one layer, both directions) -------
// 128 CTAs: dir = blk>>6, batch pair = blk&63. 800 threads, same gate/K-half
// mapping as the GEMM; 2 batch rows per CTA. ~52 weight regs per lane.
__global__ __launch_bounds__(800, 1) void lstm_scan2(
    const float* __restrict__ gx,     // (2,T,B,4H)
    const float* __restrict__ Whh,    // (2,4H,H)
    float* __restrict__ out,          // rows of (T,B), outStride floats per row
    int outStride, int outOff)
{
    int dir  = blockIdx.x >> 6;
    int pair = blockIdx.x & 63;
    int b0r = pair * 2, b1r = b0r + 1;

    int tid = threadIdx.x;
    int wp  = tid >> 5, ln = tid & 31;
    int j   = wp * 16 + (ln & 15);
    int kh  = ln >> 4;

    __shared__ float sh_h[2][104];    // padded (cols 100..103 = 0)
    __shared__ float sg[2][400];

    unsigned long long w[26];
    {
        const float* wrow = Whh + (size_t)(dir * GG + j) * HH;
        #pragma unroll
        for (int i = 0; i < 13; i++) {
            int col = 8 * i + 4 * kh;
            float4 t = make_float4(0.f, 0.f, 0.f, 0.f);
            if (col < HH) t = *(const float4*)(wrow + col);
            w[2 * i]     = pk2(t.x, t.y);
            w[2 * i + 1] = pk2(t.z, t.w);
        }
    }
    if (tid < 208) ((float*)sh_h)[tid] = 0.0f;

    float cst = 0.0f;                 // epilogue threads tid<200 only
    int bb = tid / 100, uu = tid - bb * 100;   // valid for tid<200

    int t = dir ? (TT - 1) : 0;
    size_t gxd = (size_t)dir * TT * BB * GG;
    int myrow = kh ? b1r : b0r;       // kh0 lanes fetch row0's gx, kh1 row1's
    float gval = gx[gxd + ((size_t)t * BB + myrow) * GG + j];
    __syncthreads();

    for (int it = 0; it < TT; it++) {
        unsigned long long a0 = 0, a1 = 0, a2 = 0, a3 = 0;
        #pragma unroll
        for (int i = 0; i < 13; i++) {
            int off = 8 * i + 4 * kh;
            ulonglong2 h0 = *(const ulonglong2*)&sh_h[0][off];
            ulonglong2 h1 = *(const ulonglong2*)&sh_h[1][off];
            a0 = fma2(w[2 * i],     h0.x, a0);
            a1 = fma2(w[2 * i + 1], h0.y, a1);
            a2 = fma2(w[2 * i],     h1.x, a2);
            a3 = fma2(w[2 * i + 1], h1.y, a3);
        }
        float g0 = hsum2(a0, a1) + (kh == 0 ? gval : 0.0f);
        float g1 = hsum2(a2, a3) + (kh == 1 ? gval : 0.0f);
        g0 += __shfl_xor_sync(0xffffffffu, g0, 16);
        g1 += __shfl_xor_sync(0xffffffffu, g1, 16);
        if ((ln & 16) == 0) { sg[0][j] = g0; sg[1][j] = g1; }
        if (it + 1 < TT) {            // prefetch next step's gx
            int tn = dir ? (t - 1) : (t + 1);
            gval = gx[gxd + ((size_t)tn * BB + myrow) * GG + j];
        }
        __syncthreads();
        if (tid < 200) {
            float gi = sg[bb][uu];
            float gf = sg[bb][100 + uu];
            float gg = sg[bb][200 + uu];
            float go = sg[bb][300 + uu];
            float iv = fsig(gi), fv = fsig(gf), gv = ftanh(gg), ov = fsig(go);
            cst = fv * cst + iv * gv;
            float h = ov * ftanh(cst);
            sh_h[bb][uu] = h;
            int brow = bb ? b1r : b0r;
            out[((size_t)t * BB + brow) * outStride + dir * HH + outOff + uu] = h;
        }
        __syncthreads();
        t = dir ? (t - 1) : (t + 1);
    }
}

// ---------------- launch ----------------
extern "C" void kernel_launch(void* const* d_in, const int* in_sizes, int n_in,
                              void* d_out, int out_size) {
    const float* x     = (const float*)d_in[0];
    const float* w_ih0 = (const float*)d_in[1];
    const float* w_hh0 = (const float*)d_in[2];
    const float* b0    = (const float*)d_in[3];
    const float* w_ih1 = (const float*)d_in[4];
    const float* w_hh1 = (const float*)d_in[5];
    const float* b1    = (const float*)d_in[6];
    float* out = (float*)d_out;

    float *pxT, *pgx, *pmid;
    cudaGetSymbolAddress((void**)&pxT,  g_xT);
    cudaGetSymbolAddress((void**)&pgx,  g_gx);
    cudaGetSymbolAddress((void**)&pmid, g_mid);

    // x -> xT (T,B,IN)
    transpose_x<<<dim3(TT / 32, 4, BB), dim3(32, 8)>>>(x, pxT);

    // layer 0: gx = xT @ w_ih0^T + b0 ; scan -> g_mid (stride 2H)
    gate_gemm2<100><<<148, 800>>>(pxT, IN_, w_ih0, IN_, b0, pgx);
    lstm_scan2<<<128, 800>>>(pgx, w_hh0, pmid, 2 * HH, 0);

    // layer 1: gx = mid @ w_ih1^T + b1 (single K=200 pass) ; scan -> out
    gate_gemm2<200><<<148, 800>>>(pmid, 2 * HH, w_ih1, 2 * HH, b1, pgx);
    lstm_scan2<<<128, 800>>>(pgx, w_hh1, out, 2 * HH, 0);
}

// round 3
// speedup vs baseline: 1.0564x; 1.0564x over previous
#include <cuda_runtime.h>
#include <cuda_bf16.h>
#include <cstdint>

// Problem constants
#define TT 1024
#define BB 128
#define HH 100
#define IN_ 100
#define GG 400   // 4*H

// ---------------- scratch (device globals: no allocs allowed) ----------------
__device__ float g_xT[(size_t)TT * BB * IN_];          // (T,B,IN)      52.4 MB
__device__ float g_gx[(size_t)2 * TT * BB * GG];       // (dir,T,B,4H) 419.4 MB
__device__ float g_mid[(size_t)TT * BB * 2 * HH];      // (T,B,2H)     104.9 MB

// ---------------- f32x2 helpers ----------------
__device__ __forceinline__ unsigned long long pk2(float a, float b) {
    unsigned long long r;
    asm("mov.b64 %0, {%1,%2};" : "=l"(r) : "f"(a), "f"(b));
    return r;
}
__device__ __forceinline__ unsigned long long fma2(unsigned long long a,
                                                   unsigned long long b,
                                                   unsigned long long c) {
    unsigned long long d;
    asm("fma.rn.f32x2 %0, %1, %2, %3;" : "=l"(d) : "l"(a), "l"(b), "l"(c));
    return d;
}
__device__ __forceinline__ float hsum2(unsigned long long a, unsigned long long b) {
    unsigned long long s;
    asm("add.rn.f32x2 %0, %1, %2;" : "=l"(s) : "l"(a), "l"(b));
    float lo, hi;
    asm("mov.b64 {%0,%1}, %2;" : "=f"(lo), "=f"(hi) : "l"(s));
    return lo + hi;
}

// ---------------- fast activations (MUFU-based, rel err ~1e-6) ----------------
__device__ __forceinline__ float fexp2(float x) {
    float r; asm("ex2.approx.f32 %0, %1;" : "=f"(r) : "f"(x)); return r;
}
__device__ __forceinline__ float frcpa(float x) {
    float r; asm("rcp.approx.f32 %0, %1;" : "=f"(r) : "f"(x)); return r;
}
__device__ __forceinline__ float fsig(float x) {
    return frcpa(1.0f + fexp2(-1.4426950408889634f * x));
}
__device__ __forceinline__ float ftanh(float x) {
    return fmaf(2.0f, frcpa(1.0f + fexp2(-2.8853900817779268f * x)), -1.0f);
}

// ---------------- kernel 1: transpose x (B,IN,T) -> xT (T,B,IN) ----------------
__global__ void transpose_x(const float* __restrict__ x, float* __restrict__ xT) {
    __shared__ float tile[32][33];
    int b  = blockIdx.z;
    int k0 = blockIdx.y * 32;
    int t0 = blockIdx.x * 32;
    int tx = threadIdx.x, ty = threadIdx.y;   // 32 x 8
    #pragma unroll
    for (int i = ty; i < 32; i += 8) {
        int k = k0 + i;
        tile[i][tx] = (k < IN_) ? x[((size_t)b * IN_ + k) * TT + (t0 + tx)] : 0.0f;
    }
    __syncthreads();
    #pragma unroll
    for (int i = ty; i < 32; i += 8) {
        int t = t0 + i, k = k0 + tx;
        if (k < IN_)
            xT[((size_t)t * BB + b) * IN_ + k] = tile[tx][i];
    }
}

// ---------------- kernel 2: gate GEMM, K-split register-stationary --------------
// 800 threads = 25 warps. Warp w: lanes 0-15 -> gates w*16+l (khalf 0),
// lanes 16-31 -> same gates (khalf 1). Each lane holds NBLK float4-blocks of
// W (<= 52 regs). Partial dots combined via shfl.bfly(16).
//   KF=100: blocks interleaved (2*i+kh), row padded to 104 floats (block 25 = 0)
//   KF=200: contiguous halves (kh*25+i), row = 200 floats
template<int KF>
__global__ __launch_bounds__(800, 1) void gate_gemm2(
    const float* __restrict__ src, int srcStride,
    const float* __restrict__ Wih, int wStride,
    const float* __restrict__ bias,
    float* __restrict__ out)
{
    constexpr int NBLK = (KF == 100) ? 13 : 25;
    constexpr int ROWF = (KF == 100) ? 104 : 200;
    constexpr int BPR  = ROWF / 4;       // float4 blocks per staged row
    constexpr int NLD  = 16 * BPR;       // staging loads per tile (<= 800)

    const int M   = TT * BB;             // 131072 rows per direction
    const int CPD = 74;
    const int RPC = 1776;                // rows per CTA, multiple of 16
    int dir   = blockIdx.x / CPD;
    int chunk = blockIdx.x % CPD;
    int row0  = chunk * RPC;
    int rowHi = min(row0 + RPC, M);

    int tid = threadIdx.x;
    int wp  = tid >> 5, ln = tid & 31;
    int j   = wp * 16 + (ln & 15);       // gate index 0..399
    int kh  = ln >> 4;                   // K-half

    __shared__ float stage[16][ROWF];

    // stationary weights
    unsigned long long w[2 * NBLK];
    {
        const float* wrow = Wih + (size_t)(dir * GG + j) * wStride;
        #pragma unroll
        for (int i = 0; i < NBLK; i++) {
            int col = (KF == 100) ? (8 * i + 4 * kh) : (kh * 100 + 4 * i);
            float4 t = make_float4(0.f, 0.f, 0.f, 0.f);
            if (col < KF) t = *(const float4*)(wrow + col);
            w[2 * i]     = pk2(t.x, t.y);
            w[2 * i + 1] = pk2(t.z, t.w);
        }
    }
    float bj = bias[dir * GG + j];

    // staging map + first prefetch
    int r_ld = tid / BPR;
    int c_ld = (tid % BPR) * 4;
    float4 v = make_float4(0.f, 0.f, 0.f, 0.f);
    if (tid < NLD && c_ld < KF) {
        int rr = min(row0 + r_ld, M - 1);
        v = *(const float4*)(src + (size_t)rr * srcStride + c_ld);
    }

    int ntiles = (rowHi - row0 + 15) / 16;
    for (int tI = 0; tI < ntiles; tI++) {
        __syncthreads();
        if (tid < NLD) *(float4*)&stage[r_ld][c_ld] = v;
        __syncthreads();
        if (tid < NLD && c_ld < KF && tI + 1 < ntiles) {
            int rr = min(row0 + (tI + 1) * 16 + r_ld, M - 1);
            v = *(const float4*)(src + (size_t)rr * srcStride + c_ld);
        }
        int rlim = min(16, rowHi - row0 - tI * 16);
        for (int r = 0; r < rlim; r++) {
            unsigned long long a0 = 0, a1 = 0;
            #pragma unroll
            for (int i = 0; i < NBLK; i++) {
                int off = (KF == 100) ? (8 * i + 4 * kh) : (kh * 100 + 4 * i);
                ulonglong2 hv = *(const ulonglong2*)&stage[r][off];
                a0 = fma2(w[2 * i],     hv.x, a0);
                a1 = fma2(w[2 * i + 1], hv.y, a1);
            }
            float g = hsum2(a0, a1);
            g += __shfl_xor_sync(0xffffffffu, g, 16);
            if ((ln & 16) == 0) {
                size_t orow = (size_t)(row0 + tI * 16 + r);
                out[((size_t)dir * M + orow) * GG + j] = g + bj;
            }
        }
    }
}

// ---------------- kernel 3: recurrence scan (one layer, both directions) -------
// 128 CTAs: dir = blk>>6, batch pair = blk&63. 800 threads, same gate/K-half
// mapping as the GEMM; 2 batch rows per CTA. ~52 weight regs per lane.
__global__ __launch_bounds__(800, 1) void lstm_scan2(
    const float* __restrict__ gx,     // (2,T,B,4H)
    const float* __restrict__ Whh,    // (2,4H,H)
    float* __restrict__ out,          // rows of (T,B), outStride floats per row
    int outStride, int outOff)
{
    int dir  = blockIdx.x >> 6;
    int pair = blockIdx.x & 63;
    int b0r = pair * 2, b1r = b0r + 1;

    int tid = threadIdx.x;
    int wp  = tid >> 5, ln = tid & 31;
    int j   = wp * 16 + (ln & 15);
    int kh  = ln >> 4;

    __shared__ float sh_h[2][104];    // padded (cols 100..103 = 0)
    __shared__ float sg[2][400];

    unsigned long long w[26];
    {
        const float* wrow = Whh + (size_t)(dir * GG + j) * HH;
        #pragma unroll
        for (int i = 0; i < 13; i++) {
            int col = 8 * i + 4 * kh;
            float4 t = make_float4(0.f, 0.f, 0.f, 0.f);
            if (col < HH) t = *(const float4*)(wrow + col);
            w[2 * i]     = pk2(t.x, t.y);
            w[2 * i + 1] = pk2(t.z, t.w);
        }
    }
    if (tid < 208) ((float*)sh_h)[tid] = 0.0f;

    float cst = 0.0f;                 // epilogue threads tid<200 only
    int bb = tid / 100, uu = tid - bb * 100;   // valid for tid<200

    int t = dir ? (TT - 1) : 0;
    size_t gxd = (size_t)dir * TT * BB * GG;
    int myrow = kh ? b1r : b0r;       // kh0 lanes fetch row0's gx, kh1 row1's
    float gval = gx[gxd + ((size_t)t * BB + myrow) * GG + j];
    __syncthreads();

    for (int it = 0; it < TT; it++) {
        unsigned long long a0 = 0, a1 = 0, a2 = 0, a3 = 0;
        #pragma unroll
        for (int i = 0; i < 13; i++) {
            int off = 8 * i + 4 * kh;
            ulonglong2 h0 = *(const ulonglong2*)&sh_h[0][off];
            ulonglong2 h1 = *(const ulonglong2*)&sh_h[1][off];
            a0 = fma2(w[2 * i],     h0.x, a0);
            a1 = fma2(w[2 * i + 1], h0.y, a1);
            a2 = fma2(w[2 * i],     h1.x, a2);
            a3 = fma2(w[2 * i + 1], h1.y, a3);
        }
        float g0 = hsum2(a0, a1) + (kh == 0 ? gval : 0.0f);
        float g1 = hsum2(a2, a3) + (kh == 1 ? gval : 0.0f);
        g0 += __shfl_xor_sync(0xffffffffu, g0, 16);
        g1 += __shfl_xor_sync(0xffffffffu, g1, 16);
        if ((ln & 16) == 0) { sg[0][j] = g0; sg[1][j] = g1; }
        if (it + 1 < TT) {            // prefetch next step's gx
            int tn = dir ? (t - 1) : (t + 1);
            gval = gx[gxd + ((size_t)tn * BB + myrow) * GG + j];
        }
        __syncthreads();
        if (tid < 200) {
            float gi = sg[bb][uu];
            float gf = sg[bb][100 + uu];
            float gg = sg[bb][200 + uu];
            float go = sg[bb][300 + uu];
            float iv = fsig(gi), fv = fsig(gf), gv = ftanh(gg), ov = fsig(go);
            cst = fv * cst + iv * gv;
            float h = ov * ftanh(cst);
            sh_h[bb][uu] = h;
            int brow = bb ? b1r : b0r;
            out[((size_t)t * BB + brow) * outStride + dir * HH + outOff + uu] = h;
        }
        __syncthreads();
        t = dir ? (t - 1) : (t + 1);
    }
}

// ---------------- launch ----------------
extern "C" void kernel_launch(void* const* d_in, const int* in_sizes, int n_in,
                              void* d_out, int out_size) {
    const float* x     = (const float*)d_in[0];
    const float* w_ih0 = (const float*)d_in[1];
    const float* w_hh0 = (const float*)d_in[2];
    const float* b0    = (const float*)d_in[3];
    const float* w_ih1 = (const float*)d_in[4];
    const float* w_hh1 = (const float*)d_in[5];
    const float* b1    = (const float*)d_in[6];
    float* out = (float*)d_out;

    float *pxT, *pgx, *pmid;
    cudaGetSymbolAddress((void**)&pxT,  g_xT);
    cudaGetSymbolAddress((void**)&pgx,  g_gx);
    cudaGetSymbolAddress((void**)&pmid, g_mid);

    // x -> xT (T,B,IN)
    transpose_x<<<dim3(TT / 32, 4, BB), dim3(32, 8)>>>(x, pxT);

    // layer 0: gx = xT @ w_ih0^T + b0 ; scan -> g_mid (stride 2H)
    gate_gemm2<100><<<148, 800>>>(pxT, IN_, w_ih0, IN_, b0, pgx);
    lstm_scan2<<<128, 800>>>(pgx, w_hh0, pmid, 2 * HH, 0);

    // layer 1: gx = mid @ w_ih1^T + b1 (single K=200 pass) ; scan -> out
    gate_gemm2<200><<<148, 800>>>(pmid, 2 * HH, w_ih1, 2 * HH, b1, pgx);
    lstm_scan2<<<128, 800>>>(pgx, w_hh1, out, 2 * HH, 0);
}